// round 4
// baseline (speedup 1.0000x reference)
#include <cuda_runtime.h>
#include <cuda_fp16.h>
#include <math.h>
#include <stdint.h>

#define MT    16384
#define D     1024
#define DFF   4096
#define S_LEN 4096
#define NCHUNK 32
#define CHUNK  128

// ---------------- scratch ----------------
__device__ __half g_h    [(size_t)MT * D];
__device__ __half g_Wgv  [(size_t)2 * D * D];   // column-interleaved: packed row 2j=gate j, 2j+1=val j
__device__ __half g_W1   [(size_t)DFF * D];
__device__ __half g_W2   [(size_t)D * DFF];
__device__ __half g_gbuf [(size_t)MT * D];
__device__ __half g_gvbuf[(size_t)MT * D];
__device__ float  g_xmid [(size_t)MT * D];
__device__ __half g_h2   [(size_t)MT * D];
__device__ __half g_a1   [(size_t)MT * DFF];
__device__ float  g_pg   [4 * NCHUNK * D];
__device__ float  g_pv   [4 * NCHUNK * D];

// ---------------- helpers ----------------
__device__ __forceinline__ uint32_t smem_u32(const void* p) {
    return (uint32_t)__cvta_generic_to_shared(p);
}
__device__ __forceinline__ uint32_t swz(uint32_t off) {          // SW128: Swizzle<3,4,3>
    return off ^ ((off >> 3) & 0x70);
}
__device__ __forceinline__ void cp16(uint32_t dst, const void* src) {
    asm volatile("cp.async.cg.shared.global [%0], [%1], 16;\n" :: "r"(dst), "l"(src) : "memory");
}
__device__ __forceinline__ void cp_commit() { asm volatile("cp.async.commit_group;\n" ::: "memory"); }
__device__ __forceinline__ void cp_wait0()  { asm volatile("cp.async.wait_group 0;\n" ::: "memory"); }
__device__ __forceinline__ void cp_wait1()  { asm volatile("cp.async.wait_group 1;\n" ::: "memory"); }

__device__ __forceinline__ void ldsm4(uint32_t& r0, uint32_t& r1, uint32_t& r2, uint32_t& r3, uint32_t a) {
    asm volatile("ldmatrix.sync.aligned.m8n8.x4.shared.b16 {%0,%1,%2,%3}, [%4];\n"
                 : "=r"(r0), "=r"(r1), "=r"(r2), "=r"(r3) : "r"(a));
}
__device__ __forceinline__ void mma16816(float c[4],
                                         uint32_t a0, uint32_t a1, uint32_t a2, uint32_t a3,
                                         uint32_t b0, uint32_t b1) {
    asm volatile("mma.sync.aligned.m16n8k16.row.col.f32.f16.f16.f32 "
                 "{%0,%1,%2,%3},{%4,%5,%6,%7},{%8,%9},{%0,%1,%2,%3};\n"
                 : "+f"(c[0]), "+f"(c[1]), "+f"(c[2]), "+f"(c[3])
                 : "r"(a0), "r"(a1), "r"(a2), "r"(a3), "r"(b0), "r"(b1));
}
__device__ __forceinline__ float gelu_f(float x) {
    return 0.5f * x * (1.0f + erff(x * 0.70710678118654752f));
}
__device__ __forceinline__ float sigmoid_f(float x) {
    return 1.0f / (1.0f + __expf(-x));
}

// ---------------- weight fp32 -> fp16 (plain) ----------------
__global__ void cvt_kernel(const float* __restrict__ src, __half* __restrict__ dst, int n4) {
    int i = blockIdx.x * blockDim.x + threadIdx.x;
    if (i >= n4) return;
    float4 v = ((const float4*)src)[i];
    ((__half2*)dst)[2 * i]     = __floats2half2_rn(v.x, v.y);
    ((__half2*)dst)[2 * i + 1] = __floats2half2_rn(v.z, v.w);
}

// ---------------- gate/val -> column-interleaved packed fp16 ----------------
// packed row p: p even -> gate row p/2 ; p odd -> val row p/2
__global__ void cvt_gv_kernel(const float* __restrict__ gate, const float* __restrict__ val,
                              __half* __restrict__ dst) {
    int i = blockIdx.x * blockDim.x + threadIdx.x;     // 2*D*D/4 threads
    int e = i * 4;
    int p = e >> 10;
    int c4 = (e & 1023) >> 2;
    const float* src = (p & 1) ? val : gate;
    float4 v = ((const float4*)(src + (size_t)(p >> 1) * D))[c4];
    ((__half2*)dst)[2 * i]     = __floats2half2_rn(v.x, v.y);
    ((__half2*)dst)[2 * i + 1] = __floats2half2_rn(v.z, v.w);
}

// ---------------- layernorm: one warp per row ----------------
__global__ void __launch_bounds__(256) ln_kernel(const float* __restrict__ in,
                                                 const float* __restrict__ w,
                                                 const float* __restrict__ b,
                                                 __half* __restrict__ out) {
    int row  = blockIdx.x * 8 + (threadIdx.x >> 5);
    int lane = threadIdx.x & 31;
    const float4* p = (const float4*)(in + (size_t)row * D);
    float4 v[8];
    float s = 0.f, sq = 0.f;
#pragma unroll
    for (int i = 0; i < 8; ++i) {
        v[i] = p[lane + i * 32];
        s  += v[i].x + v[i].y + v[i].z + v[i].w;
        sq += v[i].x * v[i].x + v[i].y * v[i].y + v[i].z * v[i].z + v[i].w * v[i].w;
    }
#pragma unroll
    for (int o = 16; o > 0; o >>= 1) {
        s  += __shfl_xor_sync(0xffffffffu, s, o);
        sq += __shfl_xor_sync(0xffffffffu, sq, o);
    }
    float mean = s * (1.0f / D);
    float inv  = rsqrtf(sq * (1.0f / D) - mean * mean + 1e-5f);
    __half2* o2 = (__half2*)(out + (size_t)row * D);
#pragma unroll
    for (int i = 0; i < 8; ++i) {
        int c4 = lane + i * 32;
        float4 wv = ((const float4*)w)[c4];
        float4 bv = ((const float4*)b)[c4];
        o2[c4 * 2]     = __floats2half2_rn((v[i].x - mean) * inv * wv.x + bv.x,
                                           (v[i].y - mean) * inv * wv.y + bv.y);
        o2[c4 * 2 + 1] = __floats2half2_rn((v[i].z - mean) * inv * wv.z + bv.z,
                                           (v[i].w - mean) * inv * wv.w + bv.w);
    }
}

// ---------------- 3-phase blocked scan along S ----------------
__global__ void __launch_bounds__(256) scan1_kernel() {
    int d = blockIdx.x * 256 + threadIdx.x;
    int c = blockIdx.y, b = blockIdx.z;
    size_t base = ((size_t)b * S_LEN + (size_t)c * CHUNK) * D + d;
    float sg = 0.f, sv = 0.f;
#pragma unroll 4
    for (int s = 0; s < CHUNK; ++s) {
        sg += __half2float(g_gbuf [base + (size_t)s * D]);
        sv += __half2float(g_gvbuf[base + (size_t)s * D]);
    }
    g_pg[((size_t)b * NCHUNK + c) * D + d] = sg;
    g_pv[((size_t)b * NCHUNK + c) * D + d] = sv;
}
__global__ void __launch_bounds__(256) scan2_kernel() {
    int d = blockIdx.x * 256 + threadIdx.x;
    int b = blockIdx.y;
    float rg = 0.f, rv = 0.f;
    for (int c = 0; c < NCHUNK; ++c) {
        size_t i = ((size_t)b * NCHUNK + c) * D + d;
        float tg = g_pg[i], tv = g_pv[i];
        g_pg[i] = rg; g_pv[i] = rv;
        rg += tg; rv += tv;
    }
}
__global__ void __launch_bounds__(256) scan3_kernel(const float* __restrict__ x,
                                                    float* __restrict__ xmid) {
    int d = blockIdx.x * 256 + threadIdx.x;
    int c = blockIdx.y, b = blockIdx.z;
    float ag = g_pg[((size_t)b * NCHUNK + c) * D + d];
    float av = g_pv[((size_t)b * NCHUNK + c) * D + d];
    size_t base = ((size_t)b * S_LEN + (size_t)c * CHUNK) * D + d;
#pragma unroll 4
    for (int s0 = 0; s0 < CHUNK; ++s0) {
        size_t idx = base + (size_t)s0 * D;
        int s = c * CHUNK + s0;
        ag += __half2float(g_gbuf[idx]);
        av += __half2float(g_gvbuf[idx]);
        float scale = rsqrtf((ag + 1e-6f) * ((float)(s + 1) * (1.0f / S_LEN) + 0.1f));
        xmid[idx] = x[idx] + av * scale;
    }
}

// ---------------- GEMM: C[M,N] = A[M,K]*B[N,K]^T, CTA tile 256x256, 512 thr, 3 stages ----------------
#define STAGE_BYTES 65536u       // A 32KB + B 32KB
#define SMEM_DYN    (3 * 65536 + 1024)

__device__ __forceinline__ void load_stage(uint32_t sbase, int s,
                                           const __half* A, const __half* B,
                                           int K, int bm, int bn, int kt, int tid) {
    uint32_t sa = sbase + (uint32_t)s * STAGE_BYTES;
    uint32_t sb = sa + 32768u;
    const __half* gA = A + (size_t)bm * K + (size_t)kt * 64;
    const __half* gB = B + (size_t)bn * K + (size_t)kt * 64;
#pragma unroll
    for (int i = 0; i < 4; ++i) {               // A: 256 rows x 8 x 16B
        int id = tid + 512 * i;
        int r = id >> 3, c = id & 7;
        cp16(sa + swz((uint32_t)(r * 128 + c * 16)), gA + (size_t)r * K + c * 8);
    }
#pragma unroll
    for (int i = 0; i < 4; ++i) {               // B: 256 rows x 8 x 16B
        int id = tid + 512 * i;
        int r = id >> 3, c = id & 7;
        cp16(sb + swz((uint32_t)(r * 128 + c * 16)), gB + (size_t)r * K + c * 8);
    }
    cp_commit();
}

// EPI 0: fused sigmoid/gate*val (interleaved packed weights) -> g_gbuf/g_gvbuf
// EPI 1: gelu(acc+bias) fp16 -> outH
// EPI 2: acc+bias+resid fp32 -> outF
template <int EPI>
__global__ void __launch_bounds__(512, 1) tc_gemm(const __half* __restrict__ A,
                                                  const __half* __restrict__ B,
                                                  int M, int N, int K,
                                                  const float* __restrict__ bias,
                                                  const float* __restrict__ bias2,
                                                  const float* __restrict__ resid,
                                                  __half* __restrict__ outH,
                                                  float* __restrict__ outF) {
    extern __shared__ char dsm[];
    const int tid  = threadIdx.x;
    const int warp = tid >> 5;
    const int lane = tid & 31;
    const int bm = blockIdx.y * 256;
    const int bn = blockIdx.x * 256;
    uint32_t sbase = (smem_u32(dsm) + 1023u) & ~1023u;
    const int KT = K >> 6;

    const int m0 = (warp >> 2) * 64;   // 4x4 warps, each 64x64
    const int n0 = (warp & 3) * 64;

    float acc[4][8][4];
#pragma unroll
    for (int i = 0; i < 4; ++i)
#pragma unroll
        for (int j = 0; j < 8; ++j)
#pragma unroll
            for (int q = 0; q < 4; ++q) acc[i][j][q] = 0.f;

    load_stage(sbase, 0, A, B, K, bm, bn, 0, tid);
    load_stage(sbase, 1, A, B, K, bm, bn, 1, tid);

    const uint32_t aRow  = (uint32_t)(m0 + (lane & 15));
    const uint32_t aColB = (uint32_t)((lane >> 4) * 16);
    const uint32_t bRow  = (uint32_t)(n0 + ((lane >> 4) & 1) * 8 + (lane & 7));
    const uint32_t bColB = (uint32_t)(((lane >> 3) & 1) * 16);

    for (int kt = 0; kt < KT; ++kt) {
        const int s = kt % 3;
        if (kt + 1 < KT) cp_wait1(); else cp_wait0();
        __syncthreads();

        int lt = kt + 2;
        if (lt < KT) load_stage(sbase, lt % 3, A, B, K, bm, bn, lt, tid);

        uint32_t sa = sbase + (uint32_t)s * STAGE_BYTES;
        uint32_t sb = sa + 32768u;
#pragma unroll
        for (int kk = 0; kk < 4; ++kk) {
            uint32_t a[4][4], bf[8][2];
#pragma unroll
            for (int mi = 0; mi < 4; ++mi)
                ldsm4(a[mi][0], a[mi][1], a[mi][2], a[mi][3],
                      sa + swz((aRow + mi * 16) * 128 + kk * 32 + aColB));
#pragma unroll
            for (int gi = 0; gi < 4; ++gi)
                ldsm4(bf[2 * gi][0], bf[2 * gi][1], bf[2 * gi + 1][0], bf[2 * gi + 1][1],
                      sb + swz((bRow + gi * 16) * 128 + kk * 32 + bColB));
#pragma unroll
            for (int mi = 0; mi < 4; ++mi)
#pragma unroll
                for (int ni = 0; ni < 8; ++ni)
                    mma16816(acc[mi][ni], a[mi][0], a[mi][1], a[mi][2], a[mi][3],
                             bf[ni][0], bf[ni][1]);
        }
        __syncthreads();
    }

    if (EPI == 0) {
        // fused: fragment cols (c0,c1) = (gate_j, val_j), j = col/2
        float gb8[8], vb8[8];
        int jbase = (bn + n0 + (lane & 3) * 2) >> 1;
#pragma unroll
        for (int ni = 0; ni < 8; ++ni) {
            int j = jbase + ni * 4;
            gb8[ni] = bias[j];
            vb8[ni] = bias2[j];
        }
#pragma unroll
        for (int mi = 0; mi < 4; ++mi) {
            int row0 = bm + m0 + mi * 16 + (lane >> 2);
#pragma unroll
            for (int ni = 0; ni < 8; ++ni) {
                int j = jbase + ni * 4;
                float* ap = acc[mi][ni];
                float g0 = sigmoid_f(ap[0] + gb8[ni]);
                float g1 = sigmoid_f(ap[2] + gb8[ni]);
                float v0 = ap[1] + vb8[ni];
                float v1 = ap[3] + vb8[ni];
                g_gbuf [(size_t)row0 * D + j]       = __float2half_rn(g0);
                g_gvbuf[(size_t)row0 * D + j]       = __float2half_rn(g0 * v0);
                g_gbuf [(size_t)(row0 + 8) * D + j] = __float2half_rn(g1);
                g_gvbuf[(size_t)(row0 + 8) * D + j] = __float2half_rn(g1 * v1);
            }
        }
    } else {
#pragma unroll
        for (int mi = 0; mi < 4; ++mi) {
#pragma unroll
            for (int ni = 0; ni < 8; ++ni) {
                int row = bm + m0 + mi * 16 + (lane >> 2);
                int col = bn + n0 + ni * 8 + (lane & 3) * 2;
                float* ap = acc[mi][ni];
                if (EPI == 1) {
                    float b0 = bias[col], b1 = bias[col + 1];
                    *(__half2*)(outH + (size_t)row * N + col) =
                        __floats2half2_rn(gelu_f(ap[0] + b0), gelu_f(ap[1] + b1));
                    *(__half2*)(outH + (size_t)(row + 8) * N + col) =
                        __floats2half2_rn(gelu_f(ap[2] + b0), gelu_f(ap[3] + b1));
                } else {
                    float b0 = bias[col], b1 = bias[col + 1];
                    float2 r0 = *(const float2*)(resid + (size_t)row * N + col);
                    float2 r1 = *(const float2*)(resid + (size_t)(row + 8) * N + col);
                    *(float2*)(outF + (size_t)row * N + col) =
                        make_float2(ap[0] + b0 + r0.x, ap[1] + b1 + r0.y);
                    *(float2*)(outF + (size_t)(row + 8) * N + col) =
                        make_float2(ap[2] + b0 + r1.x, ap[3] + b1 + r1.y);
                }
            }
        }
    }
}

// ---------------- launch ----------------
extern "C" void kernel_launch(void* const* d_in, const int* in_sizes, int n_in,
                              void* d_out, int out_size) {
    const float* x      = (const float*)d_in[0];
    const float* ln1_w  = (const float*)d_in[1];
    const float* ln1_b  = (const float*)d_in[2];
    const float* ln2_w  = (const float*)d_in[3];
    const float* ln2_b  = (const float*)d_in[4];
    const float* gate_w = (const float*)d_in[5];
    const float* gate_b = (const float*)d_in[6];
    const float* val_w  = (const float*)d_in[7];
    const float* val_b  = (const float*)d_in[8];
    const float* ffn1_w = (const float*)d_in[9];
    const float* ffn1_b = (const float*)d_in[10];
    const float* ffn2_w = (const float*)d_in[11];
    const float* ffn2_b = (const float*)d_in[12];
    float* out = (float*)d_out;

    void *pH, *pWgv, *pW1, *pW2, *pXmid, *pH2, *pA1;
    cudaGetSymbolAddress(&pH,    g_h);
    cudaGetSymbolAddress(&pWgv,  g_Wgv);
    cudaGetSymbolAddress(&pW1,   g_W1);
    cudaGetSymbolAddress(&pW2,   g_W2);
    cudaGetSymbolAddress(&pXmid, g_xmid);
    cudaGetSymbolAddress(&pH2,   g_h2);
    cudaGetSymbolAddress(&pA1,   g_a1);

    cudaFuncSetAttribute(tc_gemm<0>, cudaFuncAttributeMaxDynamicSharedMemorySize, SMEM_DYN);
    cudaFuncSetAttribute(tc_gemm<1>, cudaFuncAttributeMaxDynamicSharedMemorySize, SMEM_DYN);
    cudaFuncSetAttribute(tc_gemm<2>, cudaFuncAttributeMaxDynamicSharedMemorySize, SMEM_DYN);

    // 1. weights fp32 -> fp16
    cvt_gv_kernel<<<(2 * D * D / 4) / 256, 256>>>(gate_w, val_w, (__half*)pWgv);
    int n4f = DFF * D / 4;
    cvt_kernel<<<(n4f + 255) / 256, 256>>>(ffn1_w, (__half*)pW1, n4f);
    cvt_kernel<<<(n4f + 255) / 256, 256>>>(ffn2_w, (__half*)pW2, n4f);

    // 2. LN1
    ln_kernel<<<MT / 8, 256>>>(x, ln1_w, ln1_b, (__half*)pH);

    // 3. fused gate+val GEMM + sigmoid epilogue: writes g_gbuf/g_gvbuf directly
    tc_gemm<0><<<dim3(2 * D / 256, MT / 256), 512, SMEM_DYN>>>(
        (const __half*)pH, (const __half*)pWgv, MT, 2 * D, D, gate_b, val_b, nullptr,
        nullptr, nullptr);

    // 4. blocked scan + memory + residual
    scan1_kernel<<<dim3(D / 256, NCHUNK, 4), 256>>>();
    scan2_kernel<<<dim3(D / 256, 4), 256>>>();
    scan3_kernel<<<dim3(D / 256, NCHUNK, 4), 256>>>(x, (float*)pXmid);

    // 5. LN2
    ln_kernel<<<MT / 8, 256>>>((const float*)pXmid, ln2_w, ln2_b, (__half*)pH2);

    // 6. FFN1 + gelu
    tc_gemm<1><<<dim3(DFF / 256, MT / 256), 512, SMEM_DYN>>>(
        (const __half*)pH2, (const __half*)pW1, MT, DFF, D, ffn1_b, nullptr, nullptr,
        (__half*)pA1, nullptr);

    // 7. FFN2 + bias + residual
    tc_gemm<2><<<dim3(D / 256, MT / 256), 512, SMEM_DYN>>>(
        (const __half*)pA1, (const __half*)pW2, MT, D, DFF, ffn2_b, nullptr,
        (const float*)pXmid, nullptr, out);
}

// round 5
// speedup vs baseline: 2.5278x; 2.5278x over previous
#include <cuda_runtime.h>
#include <cuda_fp16.h>
#include <math.h>
#include <stdint.h>

#define MT    16384
#define D     1024
#define DFF   4096
#define S_LEN 4096
#define NCHUNK 32
#define CHUNK  128

// ---------------- scratch ----------------
__device__ __half g_h    [(size_t)MT * D];
__device__ __half g_Wgv  [(size_t)2 * D * D];   // column-interleaved: packed row 2j=gate j, 2j+1=val j
__device__ __half g_W1   [(size_t)DFF * D];
__device__ __half g_W2   [(size_t)D * DFF];
__device__ __half g_gbuf [(size_t)MT * D];
__device__ __half g_gvbuf[(size_t)MT * D];
__device__ float  g_xmid [(size_t)MT * D];
__device__ __half g_h2   [(size_t)MT * D];
__device__ __half g_a1   [(size_t)MT * DFF];
__device__ float  g_pg   [4 * NCHUNK * D];
__device__ float  g_pv   [4 * NCHUNK * D];

// ---------------- helpers ----------------
__device__ __forceinline__ uint32_t smem_u32(const void* p) {
    return (uint32_t)__cvta_generic_to_shared(p);
}
__device__ __forceinline__ uint32_t swz(uint32_t off) {          // SW128: Swizzle<3,4,3>
    return off ^ ((off >> 3) & 0x70);
}
__device__ __forceinline__ void cp16(uint32_t dst, const void* src) {
    asm volatile("cp.async.cg.shared.global [%0], [%1], 16;\n" :: "r"(dst), "l"(src) : "memory");
}
__device__ __forceinline__ void cp_commit() { asm volatile("cp.async.commit_group;\n" ::: "memory"); }
__device__ __forceinline__ void cp_wait0()  { asm volatile("cp.async.wait_group 0;\n" ::: "memory"); }
__device__ __forceinline__ void cp_wait1()  { asm volatile("cp.async.wait_group 1;\n" ::: "memory"); }
__device__ __forceinline__ void cp_wait2()  { asm volatile("cp.async.wait_group 2;\n" ::: "memory"); }

__device__ __forceinline__ void ldsm4(uint32_t& r0, uint32_t& r1, uint32_t& r2, uint32_t& r3, uint32_t a) {
    asm volatile("ldmatrix.sync.aligned.m8n8.x4.shared.b16 {%0,%1,%2,%3}, [%4];\n"
                 : "=r"(r0), "=r"(r1), "=r"(r2), "=r"(r3) : "r"(a));
}
__device__ __forceinline__ void mma16816(float c[4],
                                         uint32_t a0, uint32_t a1, uint32_t a2, uint32_t a3,
                                         uint32_t b0, uint32_t b1) {
    asm volatile("mma.sync.aligned.m16n8k16.row.col.f32.f16.f16.f32 "
                 "{%0,%1,%2,%3},{%4,%5,%6,%7},{%8,%9},{%0,%1,%2,%3};\n"
                 : "+f"(c[0]), "+f"(c[1]), "+f"(c[2]), "+f"(c[3])
                 : "r"(a0), "r"(a1), "r"(a2), "r"(a3), "r"(b0), "r"(b1));
}
__device__ __forceinline__ float gelu_f(float x) {
    return 0.5f * x * (1.0f + erff(x * 0.70710678118654752f));
}
__device__ __forceinline__ float sigmoid_f(float x) {
    return 1.0f / (1.0f + __expf(-x));
}

// ---------------- weight fp32 -> fp16 (plain) ----------------
__global__ void cvt_kernel(const float* __restrict__ src, __half* __restrict__ dst, int n4) {
    int i = blockIdx.x * blockDim.x + threadIdx.x;
    if (i >= n4) return;
    float4 v = ((const float4*)src)[i];
    ((__half2*)dst)[2 * i]     = __floats2half2_rn(v.x, v.y);
    ((__half2*)dst)[2 * i + 1] = __floats2half2_rn(v.z, v.w);
}

// ---------------- gate/val -> column-interleaved packed fp16 ----------------
__global__ void cvt_gv_kernel(const float* __restrict__ gate, const float* __restrict__ val,
                              __half* __restrict__ dst) {
    int i = blockIdx.x * blockDim.x + threadIdx.x;     // 2*D*D/4 threads
    int e = i * 4;
    int p = e >> 10;
    int c4 = (e & 1023) >> 2;
    const float* src = (p & 1) ? val : gate;
    float4 v = ((const float4*)(src + (size_t)(p >> 1) * D))[c4];
    ((__half2*)dst)[2 * i]     = __floats2half2_rn(v.x, v.y);
    ((__half2*)dst)[2 * i + 1] = __floats2half2_rn(v.z, v.w);
}

// ---------------- layernorm: one warp per row ----------------
__global__ void __launch_bounds__(256) ln_kernel(const float* __restrict__ in,
                                                 const float* __restrict__ w,
                                                 const float* __restrict__ b,
                                                 __half* __restrict__ out) {
    int row  = blockIdx.x * 8 + (threadIdx.x >> 5);
    int lane = threadIdx.x & 31;
    const float4* p = (const float4*)(in + (size_t)row * D);
    float4 v[8];
    float s = 0.f, sq = 0.f;
#pragma unroll
    for (int i = 0; i < 8; ++i) {
        v[i] = p[lane + i * 32];
        s  += v[i].x + v[i].y + v[i].z + v[i].w;
        sq += v[i].x * v[i].x + v[i].y * v[i].y + v[i].z * v[i].z + v[i].w * v[i].w;
    }
#pragma unroll
    for (int o = 16; o > 0; o >>= 1) {
        s  += __shfl_xor_sync(0xffffffffu, s, o);
        sq += __shfl_xor_sync(0xffffffffu, sq, o);
    }
    float mean = s * (1.0f / D);
    float inv  = rsqrtf(sq * (1.0f / D) - mean * mean + 1e-5f);
    __half2* o2 = (__half2*)(out + (size_t)row * D);
#pragma unroll
    for (int i = 0; i < 8; ++i) {
        int c4 = lane + i * 32;
        float4 wv = ((const float4*)w)[c4];
        float4 bv = ((const float4*)b)[c4];
        o2[c4 * 2]     = __floats2half2_rn((v[i].x - mean) * inv * wv.x + bv.x,
                                           (v[i].y - mean) * inv * wv.y + bv.y);
        o2[c4 * 2 + 1] = __floats2half2_rn((v[i].z - mean) * inv * wv.z + bv.z,
                                           (v[i].w - mean) * inv * wv.w + bv.w);
    }
}

// ---------------- 3-phase blocked scan along S ----------------
__global__ void __launch_bounds__(256) scan1_kernel() {
    int d = blockIdx.x * 256 + threadIdx.x;
    int c = blockIdx.y, b = blockIdx.z;
    size_t base = ((size_t)b * S_LEN + (size_t)c * CHUNK) * D + d;
    float sg = 0.f, sv = 0.f;
#pragma unroll 4
    for (int s = 0; s < CHUNK; ++s) {
        sg += __half2float(g_gbuf [base + (size_t)s * D]);
        sv += __half2float(g_gvbuf[base + (size_t)s * D]);
    }
    g_pg[((size_t)b * NCHUNK + c) * D + d] = sg;
    g_pv[((size_t)b * NCHUNK + c) * D + d] = sv;
}
__global__ void __launch_bounds__(256) scan2_kernel() {
    int d = blockIdx.x * 256 + threadIdx.x;
    int b = blockIdx.y;
    float rg = 0.f, rv = 0.f;
    for (int c = 0; c < NCHUNK; ++c) {
        size_t i = ((size_t)b * NCHUNK + c) * D + d;
        float tg = g_pg[i], tv = g_pv[i];
        g_pg[i] = rg; g_pv[i] = rv;
        rg += tg; rv += tv;
    }
}
__global__ void __launch_bounds__(256) scan3_kernel(const float* __restrict__ x,
                                                    float* __restrict__ xmid) {
    int d = blockIdx.x * 256 + threadIdx.x;
    int c = blockIdx.y, b = blockIdx.z;
    float ag = g_pg[((size_t)b * NCHUNK + c) * D + d];
    float av = g_pv[((size_t)b * NCHUNK + c) * D + d];
    size_t base = ((size_t)b * S_LEN + (size_t)c * CHUNK) * D + d;
#pragma unroll 4
    for (int s0 = 0; s0 < CHUNK; ++s0) {
        size_t idx = base + (size_t)s0 * D;
        int s = c * CHUNK + s0;
        ag += __half2float(g_gbuf[idx]);
        av += __half2float(g_gvbuf[idx]);
        float scale = rsqrtf((ag + 1e-6f) * ((float)(s + 1) * (1.0f / S_LEN) + 0.1f));
        xmid[idx] = x[idx] + av * scale;
    }
}

// ---------------- GEMM: C[M,N]=A[M,K]*B[N,K]^T, CTA 128x256, 256 thr, 4 stages ----------------
#define STAGE_BYTES 49152u       // A 16KB + B 32KB
#define SMEM_DYN    (4 * 49152 + 1024)

__device__ __forceinline__ void load_stage(uint32_t sbase, int s,
                                           const __half* A, const __half* B,
                                           int K, int bm, int bn, int kt, int tid) {
    uint32_t sa = sbase + (uint32_t)s * STAGE_BYTES;
    uint32_t sb = sa + 16384u;
    const __half* gA = A + (size_t)bm * K + (size_t)kt * 64;
    const __half* gB = B + (size_t)bn * K + (size_t)kt * 64;
#pragma unroll
    for (int i = 0; i < 4; ++i) {               // A: 128 rows x 8 x 16B
        int id = tid + 256 * i;
        int r = id >> 3, c = id & 7;
        cp16(sa + swz((uint32_t)(r * 128 + c * 16)), gA + (size_t)r * K + c * 8);
    }
#pragma unroll
    for (int i = 0; i < 8; ++i) {               // B: 256 rows x 8 x 16B
        int id = tid + 256 * i;
        int r = id >> 3, c = id & 7;
        cp16(sb + swz((uint32_t)(r * 128 + c * 16)), gB + (size_t)r * K + c * 8);
    }
    cp_commit();
}

// EPI 0: fused sigmoid/gate*val (interleaved packed weights) -> g_gbuf/g_gvbuf
// EPI 1: gelu(acc+bias) fp16 -> outH
// EPI 2: acc+bias+resid fp32 -> outF
template <int EPI>
__global__ void __launch_bounds__(256, 1) tc_gemm(const __half* __restrict__ A,
                                                  const __half* __restrict__ B,
                                                  int M, int N, int K,
                                                  const float* __restrict__ bias,
                                                  const float* __restrict__ bias2,
                                                  const float* __restrict__ resid,
                                                  __half* __restrict__ outH,
                                                  float* __restrict__ outF) {
    extern __shared__ char dsm[];
    const int tid  = threadIdx.x;
    const int warp = tid >> 5;
    const int lane = tid & 31;
    const int bm = blockIdx.y * 128;
    const int bn = blockIdx.x * 256;
    uint32_t sbase = (smem_u32(dsm) + 1023u) & ~1023u;
    const int KT = K >> 6;

    const int m0 = (warp >> 2) * 64;   // 2x4 warps, each 64x64
    const int n0 = (warp & 3) * 64;

    float acc[4][8][4];
#pragma unroll
    for (int i = 0; i < 4; ++i)
#pragma unroll
        for (int j = 0; j < 8; ++j)
#pragma unroll
            for (int q = 0; q < 4; ++q) acc[i][j][q] = 0.f;

    load_stage(sbase, 0, A, B, K, bm, bn, 0, tid);
    load_stage(sbase, 1, A, B, K, bm, bn, 1, tid);
    load_stage(sbase, 2, A, B, K, bm, bn, 2, tid);

    const uint32_t aRow  = (uint32_t)(m0 + (lane & 15));
    const uint32_t aColB = (uint32_t)((lane >> 4) * 16);
    const uint32_t bRow  = (uint32_t)(n0 + ((lane >> 4) & 1) * 8 + (lane & 7));
    const uint32_t bColB = (uint32_t)(((lane >> 3) & 1) * 16);

    for (int kt = 0; kt < KT; ++kt) {
        const int s = kt & 3;
        int pend = KT - 1 - kt; if (pend > 2) pend = 2;
        if (pend == 2) cp_wait2(); else if (pend == 1) cp_wait1(); else cp_wait0();
        __syncthreads();

        int lt = kt + 3;
        if (lt < KT) load_stage(sbase, lt & 3, A, B, K, bm, bn, lt, tid);

        uint32_t sa = sbase + (uint32_t)s * STAGE_BYTES;
        uint32_t sb = sa + 16384u;
#pragma unroll
        for (int kk = 0; kk < 4; ++kk) {
            uint32_t a[4][4], bf[8][2];
#pragma unroll
            for (int mi = 0; mi < 4; ++mi)
                ldsm4(a[mi][0], a[mi][1], a[mi][2], a[mi][3],
                      sa + swz((aRow + mi * 16) * 128 + kk * 32 + aColB));
#pragma unroll
            for (int gi = 0; gi < 4; ++gi)
                ldsm4(bf[2 * gi][0], bf[2 * gi][1], bf[2 * gi + 1][0], bf[2 * gi + 1][1],
                      sb + swz((bRow + gi * 16) * 128 + kk * 32 + bColB));
#pragma unroll
            for (int mi = 0; mi < 4; ++mi)
#pragma unroll
                for (int ni = 0; ni < 8; ++ni)
                    mma16816(acc[mi][ni], a[mi][0], a[mi][1], a[mi][2], a[mi][3],
                             bf[ni][0], bf[ni][1]);
        }
        __syncthreads();
    }

    if (EPI == 0) {
        // fragment cols (c0,c1) = (gate_j, val_j), j = col/2
        int jbase = (bn + n0 + (lane & 3) * 2) >> 1;
        float gb8[8], vb8[8];
#pragma unroll
        for (int ni = 0; ni < 8; ++ni) {
            int j = jbase + ni * 4;
            gb8[ni] = bias[j];
            vb8[ni] = bias2[j];
        }
#pragma unroll
        for (int mi = 0; mi < 4; ++mi) {
            int row0 = bm + m0 + mi * 16 + (lane >> 2);
#pragma unroll
            for (int ni = 0; ni < 8; ++ni) {
                int j = jbase + ni * 4;
                float* ap = acc[mi][ni];
                float g0 = sigmoid_f(ap[0] + gb8[ni]);
                float g1 = sigmoid_f(ap[2] + gb8[ni]);
                float v0 = ap[1] + vb8[ni];
                float v1 = ap[3] + vb8[ni];
                g_gbuf [(size_t)row0 * D + j]       = __float2half_rn(g0);
                g_gvbuf[(size_t)row0 * D + j]       = __float2half_rn(g0 * v0);
                g_gbuf [(size_t)(row0 + 8) * D + j] = __float2half_rn(g1);
                g_gvbuf[(size_t)(row0 + 8) * D + j] = __float2half_rn(g1 * v1);
            }
        }
    } else {
#pragma unroll
        for (int mi = 0; mi < 4; ++mi) {
#pragma unroll
            for (int ni = 0; ni < 8; ++ni) {
                int row = bm + m0 + mi * 16 + (lane >> 2);
                int col = bn + n0 + ni * 8 + (lane & 3) * 2;
                float* ap = acc[mi][ni];
                if (EPI == 1) {
                    float b0 = bias[col], b1 = bias[col + 1];
                    *(__half2*)(outH + (size_t)row * N + col) =
                        __floats2half2_rn(gelu_f(ap[0] + b0), gelu_f(ap[1] + b1));
                    *(__half2*)(outH + (size_t)(row + 8) * N + col) =
                        __floats2half2_rn(gelu_f(ap[2] + b0), gelu_f(ap[3] + b1));
                } else {
                    float b0 = bias[col], b1 = bias[col + 1];
                    float2 r0 = *(const float2*)(resid + (size_t)row * N + col);
                    float2 r1 = *(const float2*)(resid + (size_t)(row + 8) * N + col);
                    *(float2*)(outF + (size_t)row * N + col) =
                        make_float2(ap[0] + b0 + r0.x, ap[1] + b1 + r0.y);
                    *(float2*)(outF + (size_t)(row + 8) * N + col) =
                        make_float2(ap[2] + b0 + r1.x, ap[3] + b1 + r1.y);
                }
            }
        }
    }
}

// ---------------- launch ----------------
extern "C" void kernel_launch(void* const* d_in, const int* in_sizes, int n_in,
                              void* d_out, int out_size) {
    const float* x      = (const float*)d_in[0];
    const float* ln1_w  = (const float*)d_in[1];
    const float* ln1_b  = (const float*)d_in[2];
    const float* ln2_w  = (const float*)d_in[3];
    const float* ln2_b  = (const float*)d_in[4];
    const float* gate_w = (const float*)d_in[5];
    const float* gate_b = (const float*)d_in[6];
    const float* val_w  = (const float*)d_in[7];
    const float* val_b  = (const float*)d_in[8];
    const float* ffn1_w = (const float*)d_in[9];
    const float* ffn1_b = (const float*)d_in[10];
    const float* ffn2_w = (const float*)d_in[11];
    const float* ffn2_b = (const float*)d_in[12];
    float* out = (float*)d_out;

    void *pH, *pWgv, *pW1, *pW2, *pXmid, *pH2, *pA1;
    cudaGetSymbolAddress(&pH,    g_h);
    cudaGetSymbolAddress(&pWgv,  g_Wgv);
    cudaGetSymbolAddress(&pW1,   g_W1);
    cudaGetSymbolAddress(&pW2,   g_W2);
    cudaGetSymbolAddress(&pXmid, g_xmid);
    cudaGetSymbolAddress(&pH2,   g_h2);
    cudaGetSymbolAddress(&pA1,   g_a1);

    cudaFuncSetAttribute(tc_gemm<0>, cudaFuncAttributeMaxDynamicSharedMemorySize, SMEM_DYN);
    cudaFuncSetAttribute(tc_gemm<1>, cudaFuncAttributeMaxDynamicSharedMemorySize, SMEM_DYN);
    cudaFuncSetAttribute(tc_gemm<2>, cudaFuncAttributeMaxDynamicSharedMemorySize, SMEM_DYN);

    // 1. weights fp32 -> fp16
    cvt_gv_kernel<<<(2 * D * D / 4) / 256, 256>>>(gate_w, val_w, (__half*)pWgv);
    int n4f = DFF * D / 4;
    cvt_kernel<<<(n4f + 255) / 256, 256>>>(ffn1_w, (__half*)pW1, n4f);
    cvt_kernel<<<(n4f + 255) / 256, 256>>>(ffn2_w, (__half*)pW2, n4f);

    // 2. LN1
    ln_kernel<<<MT / 8, 256>>>(x, ln1_w, ln1_b, (__half*)pH);

    // 3. fused gate+val GEMM + sigmoid epilogue -> g_gbuf/g_gvbuf
    tc_gemm<0><<<dim3(2 * D / 256, MT / 128), 256, SMEM_DYN>>>(
        (const __half*)pH, (const __half*)pWgv, MT, 2 * D, D, gate_b, val_b, nullptr,
        nullptr, nullptr);

    // 4. blocked scan + memory + residual
    scan1_kernel<<<dim3(D / 256, NCHUNK, 4), 256>>>();
    scan2_kernel<<<dim3(D / 256, 4), 256>>>();
    scan3_kernel<<<dim3(D / 256, NCHUNK, 4), 256>>>(x, (float*)pXmid);

    // 5. LN2
    ln_kernel<<<MT / 8, 256>>>((const float*)pXmid, ln2_w, ln2_b, (__half*)pH2);

    // 6. FFN1 + gelu
    tc_gemm<1><<<dim3(DFF / 256, MT / 128), 256, SMEM_DYN>>>(
        (const __half*)pH2, (const __half*)pW1, MT, DFF, D, ffn1_b, nullptr, nullptr,
        (__half*)pA1, nullptr);

    // 7. FFN2 + bias + residual
    tc_gemm<2><<<dim3(D / 256, MT / 128), 256, SMEM_DYN>>>(
        (const __half*)pA1, (const __half*)pW2, MT, D, DFF, ffn2_b, nullptr,
        (const float*)pXmid, nullptr, out);
}

// round 6
// speedup vs baseline: 2.5712x; 1.0172x over previous
#include <cuda_runtime.h>
#include <cuda_fp16.h>
#include <math.h>
#include <stdint.h>

#define MT    16384
#define D     1024
#define DFF   4096
#define S_LEN 4096
#define NCHUNK 32
#define CHUNK  128

// ---------------- scratch ----------------
__device__ __half  g_h   [(size_t)MT * D];
__device__ __half  g_Wgv [(size_t)2 * D * D];   // column-interleaved: packed row 2j=gate j, 2j+1=val j
__device__ __half  g_W1  [(size_t)DFF * D];
__device__ __half  g_W2  [(size_t)D * DFF];
__device__ __half2 g_ggv [(size_t)MT * D];      // {g, g*v} interleaved
__device__ float   g_xmid[(size_t)MT * D];
__device__ __half  g_h2  [(size_t)MT * D];
__device__ __half  g_a1  [(size_t)MT * DFF];
__device__ float   g_pg  [4 * NCHUNK * D];
__device__ float   g_pv  [4 * NCHUNK * D];

// ---------------- helpers ----------------
__device__ __forceinline__ uint32_t smem_u32(const void* p) {
    return (uint32_t)__cvta_generic_to_shared(p);
}
__device__ __forceinline__ uint32_t swz(uint32_t off) {          // SW128: Swizzle<3,4,3>
    return off ^ ((off >> 3) & 0x70);
}
__device__ __forceinline__ void cp16(uint32_t dst, const void* src) {
    asm volatile("cp.async.cg.shared.global [%0], [%1], 16;\n" :: "r"(dst), "l"(src) : "memory");
}
__device__ __forceinline__ void cp_commit() { asm volatile("cp.async.commit_group;\n" ::: "memory"); }
__device__ __forceinline__ void cp_wait0()  { asm volatile("cp.async.wait_group 0;\n" ::: "memory"); }
__device__ __forceinline__ void cp_wait1()  { asm volatile("cp.async.wait_group 1;\n" ::: "memory"); }
__device__ __forceinline__ void cp_wait2()  { asm volatile("cp.async.wait_group 2;\n" ::: "memory"); }

__device__ __forceinline__ void ldsm4(uint32_t& r0, uint32_t& r1, uint32_t& r2, uint32_t& r3, uint32_t a) {
    asm volatile("ldmatrix.sync.aligned.m8n8.x4.shared.b16 {%0,%1,%2,%3}, [%4];\n"
                 : "=r"(r0), "=r"(r1), "=r"(r2), "=r"(r3) : "r"(a));
}
__device__ __forceinline__ void mma16816(float c[4],
                                         uint32_t a0, uint32_t a1, uint32_t a2, uint32_t a3,
                                         uint32_t b0, uint32_t b1) {
    asm volatile("mma.sync.aligned.m16n8k16.row.col.f32.f16.f16.f32 "
                 "{%0,%1,%2,%3},{%4,%5,%6,%7},{%8,%9},{%0,%1,%2,%3};\n"
                 : "+f"(c[0]), "+f"(c[1]), "+f"(c[2]), "+f"(c[3])
                 : "r"(a0), "r"(a1), "r"(a2), "r"(a3), "r"(b0), "r"(b1));
}
__device__ __forceinline__ float gelu_f(float x) {
    return 0.5f * x * (1.0f + erff(x * 0.70710678118654752f));
}
__device__ __forceinline__ float sigmoid_f(float x) {
    return 1.0f / (1.0f + __expf(-x));
}

// ---------------- weight fp32 -> fp16 (plain) ----------------
__global__ void cvt_kernel(const float* __restrict__ src, __half* __restrict__ dst, int n4) {
    int i = blockIdx.x * blockDim.x + threadIdx.x;
    if (i >= n4) return;
    float4 v = ((const float4*)src)[i];
    ((__half2*)dst)[2 * i]     = __floats2half2_rn(v.x, v.y);
    ((__half2*)dst)[2 * i + 1] = __floats2half2_rn(v.z, v.w);
}

// ---------------- gate/val -> column-interleaved packed fp16 ----------------
__global__ void cvt_gv_kernel(const float* __restrict__ gate, const float* __restrict__ val,
                              __half* __restrict__ dst) {
    int i = blockIdx.x * blockDim.x + threadIdx.x;     // 2*D*D/4 threads
    int e = i * 4;
    int p = e >> 10;
    int c4 = (e & 1023) >> 2;
    const float* src = (p & 1) ? val : gate;
    float4 v = ((const float4*)(src + (size_t)(p >> 1) * D))[c4];
    ((__half2*)dst)[2 * i]     = __floats2half2_rn(v.x, v.y);
    ((__half2*)dst)[2 * i + 1] = __floats2half2_rn(v.z, v.w);
}

// ---------------- layernorm: one warp per row ----------------
__global__ void __launch_bounds__(256) ln_kernel(const float* __restrict__ in,
                                                 const float* __restrict__ w,
                                                 const float* __restrict__ b,
                                                 __half* __restrict__ out) {
    int row  = blockIdx.x * 8 + (threadIdx.x >> 5);
    int lane = threadIdx.x & 31;
    const float4* p = (const float4*)(in + (size_t)row * D);
    float4 v[8];
    float s = 0.f, sq = 0.f;
#pragma unroll
    for (int i = 0; i < 8; ++i) {
        v[i] = p[lane + i * 32];
        s  += v[i].x + v[i].y + v[i].z + v[i].w;
        sq += v[i].x * v[i].x + v[i].y * v[i].y + v[i].z * v[i].z + v[i].w * v[i].w;
    }
#pragma unroll
    for (int o = 16; o > 0; o >>= 1) {
        s  += __shfl_xor_sync(0xffffffffu, s, o);
        sq += __shfl_xor_sync(0xffffffffu, sq, o);
    }
    float mean = s * (1.0f / D);
    float inv  = rsqrtf(sq * (1.0f / D) - mean * mean + 1e-5f);
    __half2* o2 = (__half2*)(out + (size_t)row * D);
#pragma unroll
    for (int i = 0; i < 8; ++i) {
        int c4 = lane + i * 32;
        float4 wv = ((const float4*)w)[c4];
        float4 bv = ((const float4*)b)[c4];
        o2[c4 * 2]     = __floats2half2_rn((v[i].x - mean) * inv * wv.x + bv.x,
                                           (v[i].y - mean) * inv * wv.y + bv.y);
        o2[c4 * 2 + 1] = __floats2half2_rn((v[i].z - mean) * inv * wv.z + bv.z,
                                           (v[i].w - mean) * inv * wv.w + bv.w);
    }
}

// ---------------- 3-phase blocked scan along S (reads interleaved {g,gv}) ----------------
__global__ void __launch_bounds__(256) scan1_kernel() {
    int d = blockIdx.x * 256 + threadIdx.x;
    int c = blockIdx.y, b = blockIdx.z;
    size_t base = ((size_t)b * S_LEN + (size_t)c * CHUNK) * D + d;
    float sg = 0.f, sv = 0.f;
#pragma unroll 4
    for (int s = 0; s < CHUNK; ++s) {
        float2 t = __half22float2(g_ggv[base + (size_t)s * D]);
        sg += t.x;
        sv += t.y;
    }
    g_pg[((size_t)b * NCHUNK + c) * D + d] = sg;
    g_pv[((size_t)b * NCHUNK + c) * D + d] = sv;
}
__global__ void __launch_bounds__(256) scan2_kernel() {
    int d = blockIdx.x * 256 + threadIdx.x;
    int b = blockIdx.y;
    float rg = 0.f, rv = 0.f;
    for (int c = 0; c < NCHUNK; ++c) {
        size_t i = ((size_t)b * NCHUNK + c) * D + d;
        float tg = g_pg[i], tv = g_pv[i];
        g_pg[i] = rg; g_pv[i] = rv;
        rg += tg; rv += tv;
    }
}
__global__ void __launch_bounds__(256) scan3_kernel(const float* __restrict__ x,
                                                    float* __restrict__ xmid) {
    int d = blockIdx.x * 256 + threadIdx.x;
    int c = blockIdx.y, b = blockIdx.z;
    float ag = g_pg[((size_t)b * NCHUNK + c) * D + d];
    float av = g_pv[((size_t)b * NCHUNK + c) * D + d];
    size_t base = ((size_t)b * S_LEN + (size_t)c * CHUNK) * D + d;
#pragma unroll 4
    for (int s0 = 0; s0 < CHUNK; ++s0) {
        size_t idx = base + (size_t)s0 * D;
        int s = c * CHUNK + s0;
        float2 t = __half22float2(g_ggv[idx]);
        ag += t.x;
        av += t.y;
        float scale = rsqrtf((ag + 1e-6f) * ((float)(s + 1) * (1.0f / S_LEN) + 0.1f));
        xmid[idx] = x[idx] + av * scale;
    }
}

// ---------------- GEMM: C[M,N]=A[M,K]*B[N,K]^T, CTA 128x256, 256 thr, 4 stages ----------------
#define STAGE_BYTES 49152u       // A 16KB + B 32KB
#define SMEM_DYN    (4 * 49152 + 1024)

__device__ __forceinline__ void load_stage(uint32_t sbase, int s,
                                           const __half* A, const __half* B,
                                           int K, int bm, int bn, int kt, int tid) {
    uint32_t sa = sbase + (uint32_t)s * STAGE_BYTES;
    uint32_t sb = sa + 16384u;
    const __half* gA = A + (size_t)bm * K + (size_t)kt * 64;
    const __half* gB = B + (size_t)bn * K + (size_t)kt * 64;
#pragma unroll
    for (int i = 0; i < 4; ++i) {               // A: 128 rows x 8 x 16B
        int id = tid + 256 * i;
        int r = id >> 3, c = id & 7;
        cp16(sa + swz((uint32_t)(r * 128 + c * 16)), gA + (size_t)r * K + c * 8);
    }
#pragma unroll
    for (int i = 0; i < 8; ++i) {               // B: 256 rows x 8 x 16B
        int id = tid + 256 * i;
        int r = id >> 3, c = id & 7;
        cp16(sb + swz((uint32_t)(r * 128 + c * 16)), gB + (size_t)r * K + c * 8);
    }
    cp_commit();
}

// EPI 0: fused sigmoid/gate*val -> g_ggv (half2 {g, g*v}), bias loaded inline (NO register arrays)
// EPI 1: gelu(acc+bias) fp16 -> outH
// EPI 2: acc+bias+resid fp32 -> outF
template <int EPI>
__global__ void __launch_bounds__(256, 1) tc_gemm(const __half* __restrict__ A,
                                                  const __half* __restrict__ B,
                                                  int M, int N, int K,
                                                  const float* __restrict__ bias,
                                                  const float* __restrict__ bias2,
                                                  const float* __restrict__ resid,
                                                  __half* __restrict__ outH,
                                                  float* __restrict__ outF) {
    extern __shared__ char dsm[];
    const int tid  = threadIdx.x;
    const int warp = tid >> 5;
    const int lane = tid & 31;
    const int bm = blockIdx.y * 128;
    const int bn = blockIdx.x * 256;
    uint32_t sbase = (smem_u32(dsm) + 1023u) & ~1023u;
    const int KT = K >> 6;

    const int m0 = (warp >> 2) * 64;   // 2x4 warps, each 64x64
    const int n0 = (warp & 3) * 64;

    float acc[4][8][4];
#pragma unroll
    for (int i = 0; i < 4; ++i)
#pragma unroll
        for (int j = 0; j < 8; ++j)
#pragma unroll
            for (int q = 0; q < 4; ++q) acc[i][j][q] = 0.f;

    load_stage(sbase, 0, A, B, K, bm, bn, 0, tid);
    load_stage(sbase, 1, A, B, K, bm, bn, 1, tid);
    load_stage(sbase, 2, A, B, K, bm, bn, 2, tid);

    const uint32_t aRow  = (uint32_t)(m0 + (lane & 15));
    const uint32_t aColB = (uint32_t)((lane >> 4) * 16);
    const uint32_t bRow  = (uint32_t)(n0 + ((lane >> 4) & 1) * 8 + (lane & 7));
    const uint32_t bColB = (uint32_t)(((lane >> 3) & 1) * 16);

    for (int kt = 0; kt < KT; ++kt) {
        const int s = kt & 3;
        int pend = KT - 1 - kt; if (pend > 2) pend = 2;
        if (pend == 2) cp_wait2(); else if (pend == 1) cp_wait1(); else cp_wait0();
        __syncthreads();

        int lt = kt + 3;
        if (lt < KT) load_stage(sbase, lt & 3, A, B, K, bm, bn, lt, tid);

        uint32_t sa = sbase + (uint32_t)s * STAGE_BYTES;
        uint32_t sb = sa + 16384u;
#pragma unroll
        for (int kk = 0; kk < 4; ++kk) {
            uint32_t a[4][4], bf[8][2];
#pragma unroll
            for (int mi = 0; mi < 4; ++mi)
                ldsm4(a[mi][0], a[mi][1], a[mi][2], a[mi][3],
                      sa + swz((aRow + mi * 16) * 128 + kk * 32 + aColB));
#pragma unroll
            for (int gi = 0; gi < 4; ++gi)
                ldsm4(bf[2 * gi][0], bf[2 * gi][1], bf[2 * gi + 1][0], bf[2 * gi + 1][1],
                      sb + swz((bRow + gi * 16) * 128 + kk * 32 + bColB));
#pragma unroll
            for (int mi = 0; mi < 4; ++mi)
#pragma unroll
                for (int ni = 0; ni < 8; ++ni)
                    mma16816(acc[mi][ni], a[mi][0], a[mi][1], a[mi][2], a[mi][3],
                             bf[ni][0], bf[ni][1]);
        }
        __syncthreads();
    }

    // epilogues — all structured like round-3 EPI1 (inline bias loads, no live arrays)
#pragma unroll
    for (int mi = 0; mi < 4; ++mi) {
#pragma unroll
        for (int ni = 0; ni < 8; ++ni) {
            int row = bm + m0 + mi * 16 + (lane >> 2);
            int col = bn + n0 + ni * 8 + (lane & 3) * 2;
            float* ap = acc[mi][ni];
            if (EPI == 0) {
                // fragment cols (c0,c1) = (gate_j, val_j); j = col/2
                int j = col >> 1;
                float gb = bias[j];
                float vb = bias2[j];
                float g0 = sigmoid_f(ap[0] + gb);
                float g1 = sigmoid_f(ap[2] + gb);
                g_ggv[(size_t)row * D + j]       = __floats2half2_rn(g0, g0 * (ap[1] + vb));
                g_ggv[(size_t)(row + 8) * D + j] = __floats2half2_rn(g1, g1 * (ap[3] + vb));
            } else if (EPI == 1) {
                float b0 = bias[col], b1 = bias[col + 1];
                *(__half2*)(outH + (size_t)row * N + col) =
                    __floats2half2_rn(gelu_f(ap[0] + b0), gelu_f(ap[1] + b1));
                *(__half2*)(outH + (size_t)(row + 8) * N + col) =
                    __floats2half2_rn(gelu_f(ap[2] + b0), gelu_f(ap[3] + b1));
            } else {
                float b0 = bias[col], b1 = bias[col + 1];
                float2 r0 = *(const float2*)(resid + (size_t)row * N + col);
                float2 r1 = *(const float2*)(resid + (size_t)(row + 8) * N + col);
                *(float2*)(outF + (size_t)row * N + col) =
                    make_float2(ap[0] + b0 + r0.x, ap[1] + b1 + r0.y);
                *(float2*)(outF + (size_t)(row + 8) * N + col) =
                    make_float2(ap[2] + b0 + r1.x, ap[3] + b1 + r1.y);
            }
        }
    }
}

// ---------------- launch ----------------
extern "C" void kernel_launch(void* const* d_in, const int* in_sizes, int n_in,
                              void* d_out, int out_size) {
    const float* x      = (const float*)d_in[0];
    const float* ln1_w  = (const float*)d_in[1];
    const float* ln1_b  = (const float*)d_in[2];
    const float* ln2_w  = (const float*)d_in[3];
    const float* ln2_b  = (const float*)d_in[4];
    const float* gate_w = (const float*)d_in[5];
    const float* gate_b = (const float*)d_in[6];
    const float* val_w  = (const float*)d_in[7];
    const float* val_b  = (const float*)d_in[8];
    const float* ffn1_w = (const float*)d_in[9];
    const float* ffn1_b = (const float*)d_in[10];
    const float* ffn2_w = (const float*)d_in[11];
    const float* ffn2_b = (const float*)d_in[12];
    float* out = (float*)d_out;

    void *pH, *pWgv, *pW1, *pW2, *pXmid, *pH2, *pA1;
    cudaGetSymbolAddress(&pH,    g_h);
    cudaGetSymbolAddress(&pWgv,  g_Wgv);
    cudaGetSymbolAddress(&pW1,   g_W1);
    cudaGetSymbolAddress(&pW2,   g_W2);
    cudaGetSymbolAddress(&pXmid, g_xmid);
    cudaGetSymbolAddress(&pH2,   g_h2);
    cudaGetSymbolAddress(&pA1,   g_a1);

    cudaFuncSetAttribute(tc_gemm<0>, cudaFuncAttributeMaxDynamicSharedMemorySize, SMEM_DYN);
    cudaFuncSetAttribute(tc_gemm<1>, cudaFuncAttributeMaxDynamicSharedMemorySize, SMEM_DYN);
    cudaFuncSetAttribute(tc_gemm<2>, cudaFuncAttributeMaxDynamicSharedMemorySize, SMEM_DYN);

    // 1. weights fp32 -> fp16
    cvt_gv_kernel<<<(2 * D * D / 4) / 256, 256>>>(gate_w, val_w, (__half*)pWgv);
    int n4f = DFF * D / 4;
    cvt_kernel<<<(n4f + 255) / 256, 256>>>(ffn1_w, (__half*)pW1, n4f);
    cvt_kernel<<<(n4f + 255) / 256, 256>>>(ffn2_w, (__half*)pW2, n4f);

    // 2. LN1
    ln_kernel<<<MT / 8, 256>>>(x, ln1_w, ln1_b, (__half*)pH);

    // 3. fused gate+val GEMM + sigmoid epilogue -> g_ggv {g, g*v}
    tc_gemm<0><<<dim3(2 * D / 256, MT / 128), 256, SMEM_DYN>>>(
        (const __half*)pH, (const __half*)pWgv, MT, 2 * D, D, gate_b, val_b, nullptr,
        nullptr, nullptr);

    // 4. blocked scan + memory + residual
    scan1_kernel<<<dim3(D / 256, NCHUNK, 4), 256>>>();
    scan2_kernel<<<dim3(D / 256, 4), 256>>>();
    scan3_kernel<<<dim3(D / 256, NCHUNK, 4), 256>>>(x, (float*)pXmid);

    // 5. LN2
    ln_kernel<<<MT / 8, 256>>>((const float*)pXmid, ln2_w, ln2_b, (__half*)pH2);

    // 6. FFN1 + gelu
    tc_gemm<1><<<dim3(DFF / 256, MT / 128), 256, SMEM_DYN>>>(
        (const __half*)pH2, (const __half*)pW1, MT, DFF, D, ffn1_b, nullptr, nullptr,
        (__half*)pA1, nullptr);

    // 7. FFN2 + bias + residual
    tc_gemm<2><<<dim3(D / 256, MT / 128), 256, SMEM_DYN>>>(
        (const __half*)pA1, (const __half*)pW2, MT, D, DFF, ffn2_b, nullptr,
        (const float*)pXmid, nullptr, out);
}